// round 6
// baseline (speedup 1.0000x reference)
#include <cuda_runtime.h>

// out[0:100]   = dot(I[row,:], p), row = inds1[m,0]*28 + inds1[m,1]
// out[100:200] = dot(J[row,:], p), P = 50000.
//
// v6: 4 rows per block (p load amortized 4x), 64-reg budget for deep load MLP,
// split-K over 12 chunks, fused last-block reduction (single launch).

#define P_DIM     50000
#define P_VEC4    (P_DIM / 4)      // 12500 float4 per row
#define SPLIT     12
#define CARD2     100
#define NOUT      (2 * CARD2)      // 200
#define RPB       4                // rows per block
#define NGROUPS   (NOUT / RPB)     // 50
#define NBLOCKS   (NGROUPS * SPLIT) // 600
#define W_IMG     28
#define NTHREADS  512
#define NWARPS    (NTHREADS / 32)

__device__ float        g_partials[NOUT * SPLIT];
__device__ unsigned int g_ticket = 0;

// 12500 = 12*1041 + 8 -> first 8 chunks have 1042 float4, rest 1041
__device__ __forceinline__ int chunk_start(int c) { return c * 1041 + (c < 8 ? c : 8); }

__global__ __launch_bounds__(NTHREADS, 2)
void gather_dot_v6(const float* __restrict__ p,
                   const float* __restrict__ I,
                   const float* __restrict__ J,
                   const int*   __restrict__ inds1,
                   const int*   __restrict__ inds2,
                   float*       __restrict__ out)
{
    const int group = blockIdx.x / SPLIT;   // 0..49
    const int chunk = blockIdx.x % SPLIT;   // 0..11
    const int mbase = group * RPB;          // 0,4,...,196 (never straddles I/J)

    const float* mat;
    const int*   ind;
    if (mbase < CARD2) { mat = I; ind = inds1 + 2 * mbase; }
    else               { mat = J; ind = inds2 + 2 * (mbase - CARD2); }

    const float4* __restrict__ pp = reinterpret_cast<const float4*>(p);
    const float4* __restrict__ r[RPB];
    #pragma unroll
    for (int k = 0; k < RPB; k++) {
        int row = __ldg(&ind[2 * k]) * W_IMG + __ldg(&ind[2 * k + 1]);
        r[k] = reinterpret_cast<const float4*>(mat + (size_t)row * P_DIM);
    }

    const int c0 = chunk_start(chunk);
    const int c1 = chunk_start(chunk + 1);

    float s0 = 0.0f, s1 = 0.0f, s2 = 0.0f, s3 = 0.0f;

    int i = c0 + threadIdx.x;
    // Unrolled-by-2 batch: 10 independent LDG.128 issued before any FFMA.
    for (; i + NTHREADS < c1; i += 2 * NTHREADS) {
        const int j = i + NTHREADS;
        float4 pA = pp[i];
        float4 pB = pp[j];
        float4 a0 = r[0][i], b0 = r[0][j];
        float4 a1 = r[1][i], b1 = r[1][j];
        float4 a2 = r[2][i], b2 = r[2][j];
        float4 a3 = r[3][i], b3 = r[3][j];
        s0 += a0.x * pA.x + a0.y * pA.y + a0.z * pA.z + a0.w * pA.w;
        s1 += a1.x * pA.x + a1.y * pA.y + a1.z * pA.z + a1.w * pA.w;
        s2 += a2.x * pA.x + a2.y * pA.y + a2.z * pA.z + a2.w * pA.w;
        s3 += a3.x * pA.x + a3.y * pA.y + a3.z * pA.z + a3.w * pA.w;
        s0 += b0.x * pB.x + b0.y * pB.y + b0.z * pB.z + b0.w * pB.w;
        s1 += b1.x * pB.x + b1.y * pB.y + b1.z * pB.z + b1.w * pB.w;
        s2 += b2.x * pB.x + b2.y * pB.y + b2.z * pB.z + b2.w * pB.w;
        s3 += b3.x * pB.x + b3.y * pB.y + b3.z * pB.z + b3.w * pB.w;
    }
    if (i < c1) {
        float4 pA = pp[i];
        float4 a0 = r[0][i];
        float4 a1 = r[1][i];
        float4 a2 = r[2][i];
        float4 a3 = r[3][i];
        s0 += a0.x * pA.x + a0.y * pA.y + a0.z * pA.z + a0.w * pA.w;
        s1 += a1.x * pA.x + a1.y * pA.y + a1.z * pA.z + a1.w * pA.w;
        s2 += a2.x * pA.x + a2.y * pA.y + a2.z * pA.z + a2.w * pA.w;
        s3 += a3.x * pA.x + a3.y * pA.y + a3.z * pA.z + a3.w * pA.w;
    }

    // Warp reduction of the 4 accumulators
    #pragma unroll
    for (int off = 16; off > 0; off >>= 1) {
        s0 += __shfl_xor_sync(0xFFFFFFFFu, s0, off);
        s1 += __shfl_xor_sync(0xFFFFFFFFu, s1, off);
        s2 += __shfl_xor_sync(0xFFFFFFFFu, s2, off);
        s3 += __shfl_xor_sync(0xFFFFFFFFu, s3, off);
    }

    __shared__ float ws[RPB][NWARPS];
    __shared__ bool  s_last;
    const int lane = threadIdx.x & 31;
    const int wid  = threadIdx.x >> 5;
    if (lane == 0) { ws[0][wid] = s0; ws[1][wid] = s1; ws[2][wid] = s2; ws[3][wid] = s3; }
    __syncthreads();

    // Warps 0..3 each finish one accumulator (16 values -> 1)
    if (wid < RPB && lane < NWARPS) {
        float v = ws[wid][lane];
        #pragma unroll
        for (int off = NWARPS / 2; off > 0; off >>= 1)
            v += __shfl_xor_sync(0xFFFFu, v, off);
        if (lane == 0)
            g_partials[(mbase + wid) * SPLIT + chunk] = v;
    }

    __threadfence();
    if (threadIdx.x == 0) {
        unsigned int t = atomicAdd(&g_ticket, 1u);
        s_last = (t == NBLOCKS - 1);
    }
    __syncthreads();

    if (s_last) {
        const int m = threadIdx.x;
        if (m < NOUT) {
            float s = 0.0f;
            #pragma unroll
            for (int c = 0; c < SPLIT; c++)
                s += __ldcg(&g_partials[m * SPLIT + c]);
            out[m] = s;
        }
        if (threadIdx.x == 0) g_ticket = 0;   // reset for next call
    }
}

extern "C" void kernel_launch(void* const* d_in, const int* in_sizes, int n_in,
                              void* d_out, int out_size)
{
    const float* p     = (const float*)d_in[0];   // [50000]
    const float* I     = (const float*)d_in[1];   // [784, 50000]
    const float* J     = (const float*)d_in[2];   // [784, 50000]
    const int*   inds1 = (const int*)  d_in[3];   // [100, 2]
    const int*   inds2 = (const int*)  d_in[4];   // [100, 2]
    float*       out   = (float*)d_out;           // [200]

    gather_dot_v6<<<NBLOCKS, NTHREADS>>>(p, I, J, inds1, inds2, out);
}

// round 7
// speedup vs baseline: 1.1875x; 1.1875x over previous
#include <cuda_runtime.h>

// out[0:100]   = dot(I[row,:], p), row = inds1[m,0]*28 + inds1[m,1]
// out[100:200] = dot(J[row,:], p), P = 50000.
//
// v7: 4 rows/block (p traffic /4), SPLIT=8, grid=400 <= conc 444 (occ 3)
// -> exactly ONE wave, no tail. Fused last-block reduction (single launch).

#define P_DIM     50000
#define P_VEC4    (P_DIM / 4)       // 12500 float4 per row
#define SPLIT     8
#define CARD2     100
#define NOUT      (2 * CARD2)       // 200
#define RPB       4                 // rows per block
#define NGROUPS   (NOUT / RPB)      // 50
#define NBLOCKS   (NGROUPS * SPLIT) // 400
#define W_IMG     28
#define NTHREADS  512
#define NWARPS    (NTHREADS / 32)

__device__ float        g_partials[NOUT * SPLIT];
__device__ unsigned int g_ticket = 0;

// 12500 = 8*1562 + 4 -> first 4 chunks have 1563 float4, rest 1562
__device__ __forceinline__ int chunk_start(int c) { return c * 1562 + (c < 4 ? c : 4); }

__global__ __launch_bounds__(NTHREADS, 3)
void gather_dot_v7(const float* __restrict__ p,
                   const float* __restrict__ I,
                   const float* __restrict__ J,
                   const int*   __restrict__ inds1,
                   const int*   __restrict__ inds2,
                   float*       __restrict__ out)
{
    const int group = blockIdx.x / SPLIT;   // 0..49
    const int chunk = blockIdx.x % SPLIT;   // 0..7
    const int mbase = group * RPB;          // 0,4,...,196 (never straddles I/J)

    const float* mat;
    const int*   ind;
    if (mbase < CARD2) { mat = I; ind = inds1 + 2 * mbase; }
    else               { mat = J; ind = inds2 + 2 * (mbase - CARD2); }

    const float4* __restrict__ pp = reinterpret_cast<const float4*>(p);
    const float4* __restrict__ r0;
    const float4* __restrict__ r1;
    const float4* __restrict__ r2;
    const float4* __restrict__ r3;
    {
        int row0 = __ldg(&ind[0]) * W_IMG + __ldg(&ind[1]);
        int row1 = __ldg(&ind[2]) * W_IMG + __ldg(&ind[3]);
        int row2 = __ldg(&ind[4]) * W_IMG + __ldg(&ind[5]);
        int row3 = __ldg(&ind[6]) * W_IMG + __ldg(&ind[7]);
        r0 = reinterpret_cast<const float4*>(mat + (size_t)row0 * P_DIM);
        r1 = reinterpret_cast<const float4*>(mat + (size_t)row1 * P_DIM);
        r2 = reinterpret_cast<const float4*>(mat + (size_t)row2 * P_DIM);
        r3 = reinterpret_cast<const float4*>(mat + (size_t)row3 * P_DIM);
    }

    const int c0 = chunk_start(chunk);
    const int c1 = chunk_start(chunk + 1);

    float s0 = 0.0f, s1 = 0.0f, s2 = 0.0f, s3 = 0.0f;

    // 1562 float4 / 512 threads -> ~3 iterations. 5 independent LDG.128/iter,
    // ~48 warps/SM at occ 3 supply the chip-level MLP.
    for (int i = c0 + (int)threadIdx.x; i < c1; i += NTHREADS) {
        float4 pv = pp[i];
        float4 a0 = r0[i];
        float4 a1 = r1[i];
        float4 a2 = r2[i];
        float4 a3 = r3[i];
        s0 += a0.x * pv.x + a0.y * pv.y + a0.z * pv.z + a0.w * pv.w;
        s1 += a1.x * pv.x + a1.y * pv.y + a1.z * pv.z + a1.w * pv.w;
        s2 += a2.x * pv.x + a2.y * pv.y + a2.z * pv.z + a2.w * pv.w;
        s3 += a3.x * pv.x + a3.y * pv.y + a3.z * pv.z + a3.w * pv.w;
    }

    // Warp reduction of the 4 accumulators
    #pragma unroll
    for (int off = 16; off > 0; off >>= 1) {
        s0 += __shfl_xor_sync(0xFFFFFFFFu, s0, off);
        s1 += __shfl_xor_sync(0xFFFFFFFFu, s1, off);
        s2 += __shfl_xor_sync(0xFFFFFFFFu, s2, off);
        s3 += __shfl_xor_sync(0xFFFFFFFFu, s3, off);
    }

    __shared__ float ws[RPB][NWARPS];
    __shared__ bool  s_last;
    const int lane = threadIdx.x & 31;
    const int wid  = threadIdx.x >> 5;
    if (lane == 0) { ws[0][wid] = s0; ws[1][wid] = s1; ws[2][wid] = s2; ws[3][wid] = s3; }
    __syncthreads();

    // Warps 0..3 each finish one accumulator (16 values -> 1)
    if (wid < RPB && lane < NWARPS) {
        float v = ws[wid][lane];
        #pragma unroll
        for (int off = NWARPS / 2; off > 0; off >>= 1)
            v += __shfl_xor_sync(0xFFFFu, v, off);
        if (lane == 0)
            g_partials[(mbase + wid) * SPLIT + chunk] = v;
    }

    // Fused final reduction: last block to finish sums the partials.
    __threadfence();
    if (threadIdx.x == 0) {
        unsigned int t = atomicAdd(&g_ticket, 1u);
        s_last = (t == NBLOCKS - 1);
    }
    __syncthreads();

    if (s_last) {
        const int m = threadIdx.x;
        if (m < NOUT) {
            float s = 0.0f;
            #pragma unroll
            for (int c = 0; c < SPLIT; c++)
                s += __ldcg(&g_partials[m * SPLIT + c]);
            out[m] = s;
        }
        if (threadIdx.x == 0) g_ticket = 0;   // reset for next call
    }
}

extern "C" void kernel_launch(void* const* d_in, const int* in_sizes, int n_in,
                              void* d_out, int out_size)
{
    const float* p     = (const float*)d_in[0];   // [50000]
    const float* I     = (const float*)d_in[1];   // [784, 50000]
    const float* J     = (const float*)d_in[2];   // [784, 50000]
    const int*   inds1 = (const int*)  d_in[3];   // [100, 2]
    const int*   inds2 = (const int*)  d_in[4];   // [100, 2]
    float*       out   = (float*)d_out;           // [200]

    gather_dot_v7<<<NBLOCKS, NTHREADS>>>(p, I, J, inds1, inds2, out);
}